// round 12
// baseline (speedup 1.0000x reference)
#include <cuda_runtime.h>
#include <cuda_fp16.h>
#include <cstdint>
#include <float.h>

#define BB 4
#define SS 2048
#define HH 1024

// ---------------- scratch (allocation-free) ----------------
__device__ __half g_q [(size_t)BB * SS * HH];
__device__ __half g_k [(size_t)BB * SS * HH];
__device__ __half g_v [(size_t)BB * SS * HH];
__device__ __half g_vt[(size_t)BB * SS * HH];
__device__ __half g_po[(size_t)BB * SS * HH];
__device__ float  g_attn[(size_t)BB * SS * SS];    // fp32 scores/attn
__device__ __half g_attn16[(size_t)BB * SS * SS];  // fp16 attn (PV operand)
__device__ __half g_xh [(size_t)BB * SS * HH];     // fp16 x
__device__ __half g_wh [(size_t)4 * HH * HH];      // fp16 Wq,Wk,Wv,Wo (contiguous)

__device__ __forceinline__ uint32_t smem_u32(const void* p) {
    uint32_t a;
    asm("{ .reg .u64 t; cvta.to.shared.u64 t, %1; cvt.u32.u64 %0, t; }" : "=r"(a) : "l"(p));
    return a;
}
__device__ __forceinline__ void cp_async16(uint32_t saddr, const void* gptr) {
    asm volatile("cp.async.cg.shared.global [%0], [%1], 16;"
                 :: "r"(saddr), "l"(gptr) : "memory");
}
#define CP_COMMIT() asm volatile("cp.async.commit_group;" ::: "memory")

#define LDSM_X4(r0, r1, r2, r3, addr)                                          \
    asm volatile("ldmatrix.sync.aligned.m8n8.x4.shared.b16 {%0,%1,%2,%3}, [%4];" \
        : "=r"(r0), "=r"(r1), "=r"(r2), "=r"(r3) : "r"(addr))

__device__ __forceinline__ void mma_f16(float& c0, float& c1, float& c2, float& c3,
                                        uint32_t a0, uint32_t a1, uint32_t a2, uint32_t a3,
                                        uint32_t b0, uint32_t b1) {
    asm volatile(
        "mma.sync.aligned.m16n8k16.row.col.f32.f16.f16.f32 "
        "{%0,%1,%2,%3}, {%4,%5,%6,%7}, {%8,%9}, {%0,%1,%2,%3};"
        : "+f"(c0), "+f"(c1), "+f"(c2), "+f"(c3)
        : "r"(a0), "r"(a1), "r"(a2), "r"(a3), "r"(b0), "r"(b1));
}

// ---------------------------------------------------------------------------
// half-convert copies (x single; weights batched over grid.y)
// ---------------------------------------------------------------------------
__global__ __launch_bounds__(256) void half_copy_kernel(
    const float* __restrict__ in, __half* __restrict__ out, int n4)
{
    int i = blockIdx.x * 256 + threadIdx.x;
    if (i < n4) {
        float4 v = reinterpret_cast<const float4*>(in)[i];
        __half2 lo = __floats2half2_rn(v.x, v.y);
        __half2 hi = __floats2half2_rn(v.z, v.w);
        uint2 pk;
        pk.x = *reinterpret_cast<uint32_t*>(&lo);
        pk.y = *reinterpret_cast<uint32_t*>(&hi);
        reinterpret_cast<uint2*>(out)[i] = pk;
    }
}

__global__ __launch_bounds__(256) void half_copy_w_kernel(
    const float* __restrict__ w0, const float* __restrict__ w1,
    const float* __restrict__ w2, const float* __restrict__ w3,
    __half* __restrict__ out, int n4)
{
    const float* in = (blockIdx.y == 0) ? w0 : (blockIdx.y == 1) ? w1
                    : (blockIdx.y == 2) ? w2 : w3;
    __half* o = out + (size_t)blockIdx.y * n4 * 4;
    int i = blockIdx.x * 256 + threadIdx.x;
    if (i < n4) {
        float4 v = reinterpret_cast<const float4*>(in)[i];
        __half2 lo = __floats2half2_rn(v.x, v.y);
        __half2 hi = __floats2half2_rn(v.z, v.w);
        uint2 pk;
        pk.x = *reinterpret_cast<uint32_t*>(&lo);
        pk.y = *reinterpret_cast<uint32_t*>(&hi);
        reinterpret_cast<uint2*>(o)[i] = pk;
    }
}

// ---------------------------------------------------------------------------
// NT fp16 tensor-core GEMM: C[M,N] = A[M,K] @ B^T (+bias fp32)
// CTA tile 128x128x64(halves), 8 warps (2x4), warp tile 64x32, m16n8k16,
// ldmatrix.x4 fragments, 3-stage BK=64 cp.async pipeline (wait_group 1 in
// steady state: one chunk always in flight under math), dynamic smem 108KB,
// __launch_bounds__(256,2) -> 2 CTAs/SM (221KB total smem/SM).
//   TRIMAP: grid.x enumerates lower-triangular 128-tile pairs (scores)
//   TRIK  : limit K to (by+1)*128 (triangular attn in PV); heavy tiles first
//   QKV3  : N=3*1024 fused projection; epilogue routes to C/C1/C2 by n-range
//   SCALE : multiply output by 1/32 (scores pre-scaling for softmax)
// Requires M%128==0, N%128==0, K%64==0.
// ---------------------------------------------------------------------------
#define LDSH 72                         // halves per smem row (64 + 8 pad)
#define STAGE_B (128 * LDSH * 2)        // bytes per operand stage (18432)
#define GSMEM3 (6 * STAGE_B)            // 3 stages x (A+B) = 110592 bytes

template <typename OutT, bool HASBIAS, bool TRIMAP, bool TRIK, bool QKV3, bool SCALE>
__global__ __launch_bounds__(256, 2) void mma_gemm_nt(
    const __half* __restrict__ A, const __half* __restrict__ B,
    const float* __restrict__ bias, OutT* __restrict__ C,
    int M, int N, int K,
    long long strA, long long strB, long long strC,
    OutT* __restrict__ C1, OutT* __restrict__ C2,
    const float* __restrict__ bias1, const float* __restrict__ bias2)
{
    int bx, by;
    if (TRIMAP) {
        const int idx = blockIdx.x;
        int r = (int)((sqrtf(8.0f * idx + 1.0f) - 1.0f) * 0.5f);
        while ((r + 1) * (r + 2) / 2 <= idx) r++;
        while (r * (r + 1) / 2 > idx) r--;
        by = r;
        bx = idx - r * (r + 1) / 2;
    } else {
        bx = blockIdx.x;
        by = TRIK ? (gridDim.y - 1 - blockIdx.y) : blockIdx.y;  // heavy first
    }

    extern __shared__ __half smh[];

    const int tid  = threadIdx.x;
    const int wid  = tid >> 5;
    const int lane = tid & 31;
    const int g    = lane >> 2;
    const int tig  = lane & 3;
    const int m0   = by * 128;
    const int n0   = bx * 128;
    const int wm   = (wid >> 2) * 64;   // 0 or 64
    const int wn   = (wid & 3) * 32;    // 0,32,64,96

    A += (long long)blockIdx.z * strA;
    B += (long long)blockIdx.z * strB;

    const int Kend = TRIK ? min(K, (by + 1) * 128) : K;
    const int T = Kend >> 6;  // 64-half k-chunks (>= 2 for all shapes here)

    const uint32_t sBase = smem_u32(smh);
    // stage s: A at sBase + s*2*STAGE_B, B at +STAGE_B

    // loader: 128 rows x 8 chunks(16B) per operand = 1024 chunks -> 4/thread
    const int lr0 = tid >> 3;           // 0..31 (+32*it)
    const int lc0 = tid & 7;            // 16B chunk in 128B row

    const int sel  = lane >> 3;
    const int srow = lane & 7;
    const int a_row  = wm + ((sel & 1) << 3) + srow;
    const int a_colh = (sel >> 1) << 3;
    const int b_row  = wn + (sel << 3) + srow;

    float acc[4][4][4];
#pragma unroll
    for (int i = 0; i < 4; i++)
#pragma unroll
        for (int j = 0; j < 4; j++)
#pragma unroll
            for (int r = 0; r < 4; r++) acc[i][j][r] = 0.0f;

    // ---- preload chunks 0 and 1 into stages 0 and 1 ----
#pragma unroll
    for (int p = 0; p < 2; p++) {
        if (p < T) {
            const int k0 = p << 6;
            const uint32_t sa = sBase + (uint32_t)p * (2 * STAGE_B);
            const uint32_t sb = sa + STAGE_B;
#pragma unroll
            for (int it = 0; it < 4; it++) {
                const int row = lr0 + 32 * it;
                cp_async16(sa + (uint32_t)(row * LDSH + lc0 * 8) * 2,
                           A + (size_t)(m0 + row) * K + k0 + lc0 * 8);
                cp_async16(sb + (uint32_t)(row * LDSH + lc0 * 8) * 2,
                           B + (size_t)(n0 + row) * K + k0 + lc0 * 8);
            }
        }
        CP_COMMIT();  // commit even if empty to keep group accounting simple
    }

    int stage = 0;
    for (int t = 0; t < T; t++) {
        // chunk t resident; chunk t+1 may stay in flight
        if (t + 1 < T) {
            asm volatile("cp.async.wait_group 1;" ::: "memory");
        } else {
            asm volatile("cp.async.wait_group 0;" ::: "memory");
        }
        __syncthreads();  // all warps done with math(t-1) -> its stage is free

        if (t + 2 < T) {
            const int ns = (stage + 2 >= 3) ? stage - 1 : stage + 2;
            const int k0 = (t + 2) << 6;
            const uint32_t sa = sBase + (uint32_t)ns * (2 * STAGE_B);
            const uint32_t sb = sa + STAGE_B;
#pragma unroll
            for (int it = 0; it < 4; it++) {
                const int row = lr0 + 32 * it;
                cp_async16(sa + (uint32_t)(row * LDSH + lc0 * 8) * 2,
                           A + (size_t)(m0 + row) * K + k0 + lc0 * 8);
                cp_async16(sb + (uint32_t)(row * LDSH + lc0 * 8) * 2,
                           B + (size_t)(n0 + row) * K + k0 + lc0 * 8);
            }
            CP_COMMIT();
        }

        const uint32_t aB = sBase + (uint32_t)stage * (2 * STAGE_B);
        const uint32_t bB = aB + STAGE_B;
#pragma unroll
        for (int kk = 0; kk < 64; kk += 16) {
            uint32_t af[4][4], bf[4][2];
#pragma unroll
            for (int i = 0; i < 4; i++) {
                const uint32_t ad = aB + (uint32_t)((a_row + 16 * i) * LDSH + kk + a_colh) * 2;
                LDSM_X4(af[i][0], af[i][1], af[i][2], af[i][3], ad);
            }
            {
                const uint32_t bd = bB + (uint32_t)(b_row * LDSH + kk) * 2;
                LDSM_X4(bf[0][0], bf[1][0], bf[2][0], bf[3][0], bd);
                LDSM_X4(bf[0][1], bf[1][1], bf[2][1], bf[3][1], bd + 16);
            }
#pragma unroll
            for (int i = 0; i < 4; i++)
#pragma unroll
                for (int j = 0; j < 4; j++)
                    mma_f16(acc[i][j][0], acc[i][j][1], acc[i][j][2], acc[i][j][3],
                            af[i][0], af[i][1], af[i][2], af[i][3],
                            bf[j][0], bf[j][1]);
        }
        stage = (stage + 1 == 3) ? 0 : stage + 1;
    }

    // ---- epilogue (QKV3 routes by n-range; SCALE pre-multiplies) ----
    OutT* dstp = C;
    const float* bp = bias;
    int ncol0 = n0;
    int NC = N;
    if (QKV3) {
        const int s = n0 >> 10;
        dstp = (s == 0) ? C : (s == 1) ? C1 : C2;
        bp   = (s == 0) ? bias : (s == 1) ? bias1 : bias2;
        ncol0 = n0 & 1023;
        NC = HH;
    }
    dstp += (long long)blockIdx.z * strC;

#pragma unroll
    for (int i = 0; i < 4; i++) {
        const int r0 = m0 + wm + i * 16 + g;
#pragma unroll
        for (int j = 0; j < 4; j++) {
            const int col = ncol0 + wn + j * 8 + 2 * tig;
            float v00 = acc[i][j][0], v01 = acc[i][j][1];
            float v10 = acc[i][j][2], v11 = acc[i][j][3];
            if (HASBIAS) {
                const float b0 = bp[col], b1 = bp[col + 1];
                v00 += b0; v01 += b1; v10 += b0; v11 += b1;
            }
            if (SCALE) {
                v00 *= 0.03125f; v01 *= 0.03125f;
                v10 *= 0.03125f; v11 *= 0.03125f;
            }
            if (sizeof(OutT) == 2) {
                __half2 h0 = __floats2half2_rn(v00, v01);
                __half2 h1 = __floats2half2_rn(v10, v11);
                *reinterpret_cast<__half2*>((__half*)dstp + (size_t)r0 * NC + col) = h0;
                *reinterpret_cast<__half2*>((__half*)dstp + (size_t)(r0 + 8) * NC + col) = h1;
            } else {
                *reinterpret_cast<float2*>((float*)dstp + (size_t)r0 * NC + col) =
                    make_float2(v00, v01);
                *reinterpret_cast<float2*>((float*)dstp + (size_t)(r0 + 8) * NC + col) =
                    make_float2(v10, v11);
            }
        }
    }
}

// ---------------------------------------------------------------------------
// fp16 transpose per batch: out[b][h][s] = in[b][s][h]
// ---------------------------------------------------------------------------
__global__ __launch_bounds__(256) void transpose_kernel(
    const __half* __restrict__ in, __half* __restrict__ out)
{
    __shared__ __half tile[32][34];
    const int b = blockIdx.z;
    const int s0 = blockIdx.x * 32;
    const int h0 = blockIdx.y * 32;
    const __half* ip = in + (size_t)b * SS * HH;
    __half* op = out + (size_t)b * SS * HH;
    const int tx = threadIdx.x & 31;
    const int ty = threadIdx.x >> 5;
#pragma unroll
    for (int r = ty; r < 32; r += 8)
        tile[r][tx] = ip[(size_t)(s0 + r) * HH + h0 + tx];
    __syncthreads();
#pragma unroll
    for (int r = ty; r < 32; r += 8)
        op[(size_t)(h0 + r) * SS + s0 + tx] = tile[tx][r];
}

// ---------------------------------------------------------------------------
// 2-pass online row softmax with causal + key mask.
// Scores arrive PRE-SCALED (GEMM epilogue did *1/32).
// ---------------------------------------------------------------------------
__global__ __launch_bounds__(256) void softmax_kernel(
    float* __restrict__ attn, __half* __restrict__ attn16,
    const int* __restrict__ mask)
{
    const int row = blockIdx.x;
    const int b = row >> 11;
    const int i = row & (SS - 1);
    float* p = attn + (size_t)b * SS * SS + (size_t)i * SS;
    __half* p16 = attn16 + (size_t)b * SS * SS + (size_t)i * SS;
    const int* mrow = mask + (size_t)b * SS;
    const int tid = threadIdx.x;

    float m = -FLT_MAX, s = 0.0f;
    for (int j = tid; j <= i; j += 256) {
        if (mrow[j] != 0) {
            float v = p[j];
            if (v > m) { s = s * __expf(m - v) + 1.0f; m = v; }
            else       { s += __expf(v - m); }
        }
    }

    __shared__ float sm[256], ss[256];
    sm[tid] = m; ss[tid] = s;
    __syncthreads();
    for (int st = 128; st > 0; st >>= 1) {
        if (tid < st) {
            float m1 = sm[tid], s1 = ss[tid];
            float m2 = sm[tid + st], s2 = ss[tid + st];
            float M = fmaxf(m1, m2);
            ss[tid] = s1 * __expf(m1 - M) + s2 * __expf(m2 - M);
            sm[tid] = M;
        }
        __syncthreads();
    }
    const float M = sm[0], S = ss[0];

    if (S == 0.0f) {  // fully masked row -> uniform (matches reference)
        const float u = 1.0f / SS;
        const __half uh = __float2half_rn(u);
        for (int j = tid; j < SS; j += 256) { p[j] = u; p16[j] = uh; }
        return;
    }

    const float inv = 1.0f / S;
    for (int j = tid; j <= i; j += 256) {
        float v = (mrow[j] != 0) ? __expf(p[j] - M) * inv : 0.0f;
        p[j] = v;
        p16[j] = __float2half_rn(v);
    }
    const __half z = __float2half_rn(0.0f);
    for (int j = i + 1 + tid; j < SS; j += 256) { p[j] = 0.0f; p16[j] = z; }
}

// ---------------------------------------------------------------------------
extern "C" void kernel_launch(void* const* d_in, const int* in_sizes, int n_in,
                              void* d_out, int out_size)
{
    const float* x    = (const float*)d_in[0];
    const int*   mask = (const int*)  d_in[1];
    const float* Wq   = (const float*)d_in[2];
    const float* bq   = (const float*)d_in[3];
    const float* Wk   = (const float*)d_in[4];
    const float* bk   = (const float*)d_in[5];
    const float* Wv   = (const float*)d_in[6];
    const float* bv   = (const float*)d_in[7];
    const float* Wo   = (const float*)d_in[8];
    const float* bo   = (const float*)d_in[9];

    __half *q, *k, *v, *vt, *po, *attn16, *xh, *wh;
    float *attn_scratch;
    cudaGetSymbolAddress((void**)&q,  g_q);
    cudaGetSymbolAddress((void**)&k,  g_k);
    cudaGetSymbolAddress((void**)&v,  g_v);
    cudaGetSymbolAddress((void**)&vt, g_vt);
    cudaGetSymbolAddress((void**)&po, g_po);
    cudaGetSymbolAddress((void**)&attn_scratch, g_attn);
    cudaGetSymbolAddress((void**)&attn16, g_attn16);
    cudaGetSymbolAddress((void**)&xh, g_xh);
    cudaGetSymbolAddress((void**)&wh, g_wh);

    const long long OUT_N  = (long long)BB * SS * HH;
    const long long ATTN_N = (long long)BB * SS * SS;

    float* out_dst  = (float*)d_out;
    float* attn_dst = attn_scratch;
    if ((long long)out_size >= OUT_N + ATTN_N) {
        attn_dst = (float*)d_out + OUT_N;
    } else if ((long long)out_size == ATTN_N) {
        attn_dst = (float*)d_out;
        out_dst  = attn_scratch;  // unused sink
    }

    const int M_TOK = BB * SS;  // 8192
    __half* Woh = wh + (size_t)3 * HH * HH;

    cudaFuncSetAttribute(mma_gemm_nt<__half, true,  false, false, true,  false>,
        cudaFuncAttributeMaxDynamicSharedMemorySize, GSMEM3);
    cudaFuncSetAttribute(mma_gemm_nt<float,  false, true,  false, false, true>,
        cudaFuncAttributeMaxDynamicSharedMemorySize, GSMEM3);
    cudaFuncSetAttribute(mma_gemm_nt<__half, false, false, true,  false, false>,
        cudaFuncAttributeMaxDynamicSharedMemorySize, GSMEM3);
    cudaFuncSetAttribute(mma_gemm_nt<float,  true,  false, false, false, false>,
        cudaFuncAttributeMaxDynamicSharedMemorySize, GSMEM3);

    // 0) fp16 operand conversion
    {
        const int xn4 = (BB * SS * HH) / 4;
        const int wn4 = (HH * HH) / 4;
        half_copy_kernel<<<(xn4 + 255) / 256, 256>>>(x, xh, xn4);
        dim3 wg((wn4 + 255) / 256, 4);
        half_copy_w_kernel<<<wg, 256>>>(Wq, Wk, Wv, Wo, wh, wn4);
    }

    // 1) fused QKV projection: [8192,1024] @ [3072,1024]^T, routed to q/k/v
    {
        dim3 grid(3 * HH / 128, M_TOK / 128, 1);
        mma_gemm_nt<__half, true, false, false, true, false><<<grid, 256, GSMEM3>>>(
            xh, wh, bq, q, M_TOK, 3 * HH, HH, 0, 0, 0,
            k, v, bk, bv);
    }

    // 2) V^T (fp16) so PV is NT
    {
        dim3 grid(SS / 32, HH / 32, BB);
        transpose_kernel<<<grid, 256>>>(v, vt);
    }

    // 3) scores = (Q @ K^T)/32; triangular grid over 128x128 tiles
    {
        const int ntiles = (SS / 128) * (SS / 128 + 1) / 2;  // 136
        dim3 grid(ntiles, 1, BB);
        mma_gemm_nt<float, false, true, false, false, true><<<grid, 256, GSMEM3>>>(
            q, k, nullptr, attn_dst, SS, SS, HH,
            (long long)SS * HH, (long long)SS * HH, (long long)SS * SS,
            nullptr, nullptr, nullptr, nullptr);
    }

    // 4) softmax (fp32 attn output + fp16 attn for PV)
    softmax_kernel<<<BB * SS, 256>>>(attn_dst, attn16, mask);

    // 5) PV: attn16 @ V, triangular K, heavy tiles first -> fp16 po
    {
        dim3 grid(HH / 128, SS / 128, BB);
        mma_gemm_nt<__half, false, false, true, false, false><<<grid, 256, GSMEM3>>>(
            attn16, vt, nullptr, po, SS, HH, SS,
            (long long)SS * SS, (long long)SS * HH, (long long)SS * HH,
            nullptr, nullptr, nullptr, nullptr);
    }

    // 6) output projection -> fp32 out + bias
    {
        dim3 grid(HH / 128, M_TOK / 128, 1);
        mma_gemm_nt<float, true, false, false, false, false><<<grid, 256, GSMEM3>>>(
            po, Woh, bo, out_dst, M_TOK, HH, HH, 0, 0, 0,
            nullptr, nullptr, nullptr, nullptr);
    }
}

// round 14
// speedup vs baseline: 1.0144x; 1.0144x over previous
#include <cuda_runtime.h>
#include <cuda_fp16.h>
#include <cstdint>
#include <float.h>

#define BB 4
#define SS 2048
#define HH 1024

// ---------------- scratch (allocation-free) ----------------
__device__ __half g_q [(size_t)BB * SS * HH];
__device__ __half g_k [(size_t)BB * SS * HH];
__device__ __half g_vt[(size_t)BB * SS * HH];      // V^T, produced by QKV epilogue
__device__ __half g_po[(size_t)BB * SS * HH];
__device__ float  g_attn[(size_t)BB * SS * SS];    // fp32 scores/attn
__device__ __half g_attn16[(size_t)BB * SS * SS];  // fp16 attn (PV operand)
__device__ __half g_xh [(size_t)BB * SS * HH];     // fp16 x
__device__ __half g_wh [(size_t)4 * HH * HH];      // fp16 Wq,Wk,Wv,Wo (contiguous)

__device__ __forceinline__ uint32_t smem_u32(const void* p) {
    uint32_t a;
    asm("{ .reg .u64 t; cvta.to.shared.u64 t, %1; cvt.u32.u64 %0, t; }" : "=r"(a) : "l"(p));
    return a;
}
__device__ __forceinline__ void cp_async16(uint32_t saddr, const void* gptr) {
    asm volatile("cp.async.cg.shared.global [%0], [%1], 16;"
                 :: "r"(saddr), "l"(gptr) : "memory");
}
#define CP_COMMIT() asm volatile("cp.async.commit_group;" ::: "memory")

#define LDSM_X4(r0, r1, r2, r3, addr)                                          \
    asm volatile("ldmatrix.sync.aligned.m8n8.x4.shared.b16 {%0,%1,%2,%3}, [%4];" \
        : "=r"(r0), "=r"(r1), "=r"(r2), "=r"(r3) : "r"(addr))

__device__ __forceinline__ void mma_f16(float& c0, float& c1, float& c2, float& c3,
                                        uint32_t a0, uint32_t a1, uint32_t a2, uint32_t a3,
                                        uint32_t b0, uint32_t b1) {
    asm volatile(
        "mma.sync.aligned.m16n8k16.row.col.f32.f16.f16.f32 "
        "{%0,%1,%2,%3}, {%4,%5,%6,%7}, {%8,%9}, {%0,%1,%2,%3};"
        : "+f"(c0), "+f"(c1), "+f"(c2), "+f"(c3)
        : "r"(a0), "r"(a1), "r"(a2), "r"(a3), "r"(b0), "r"(b1));
}

// ---------------------------------------------------------------------------
// half-convert copies (x single; weights batched over grid.y)
// ---------------------------------------------------------------------------
__global__ __launch_bounds__(256) void half_copy_kernel(
    const float* __restrict__ in, __half* __restrict__ out, int n4)
{
    int i = blockIdx.x * 256 + threadIdx.x;
    if (i < n4) {
        float4 v = reinterpret_cast<const float4*>(in)[i];
        __half2 lo = __floats2half2_rn(v.x, v.y);
        __half2 hi = __floats2half2_rn(v.z, v.w);
        uint2 pk;
        pk.x = *reinterpret_cast<uint32_t*>(&lo);
        pk.y = *reinterpret_cast<uint32_t*>(&hi);
        reinterpret_cast<uint2*>(out)[i] = pk;
    }
}

__global__ __launch_bounds__(256) void half_copy_w_kernel(
    const float* __restrict__ w0, const float* __restrict__ w1,
    const float* __restrict__ w2, const float* __restrict__ w3,
    __half* __restrict__ out, int n4)
{
    const float* in = (blockIdx.y == 0) ? w0 : (blockIdx.y == 1) ? w1
                    : (blockIdx.y == 2) ? w2 : w3;
    __half* o = out + (size_t)blockIdx.y * n4 * 4;
    int i = blockIdx.x * 256 + threadIdx.x;
    if (i < n4) {
        float4 v = reinterpret_cast<const float4*>(in)[i];
        __half2 lo = __floats2half2_rn(v.x, v.y);
        __half2 hi = __floats2half2_rn(v.z, v.w);
        uint2 pk;
        pk.x = *reinterpret_cast<uint32_t*>(&lo);
        pk.y = *reinterpret_cast<uint32_t*>(&hi);
        reinterpret_cast<uint2*>(o)[i] = pk;
    }
}

// ---------------------------------------------------------------------------
// NT fp16 tensor-core GEMM: C[M,N] = A[M,K] @ B^T (+bias fp32)
// CTA tile 128x128x64(halves), 8 warps (2x4), warp tile 64x32, m16n8k16,
// ldmatrix.x4 fragments, double-buffered BK=64 chunks, dynamic smem 72KB,
// __launch_bounds__(256,2) -> 2 CTAs/SM.
//   TRIMAP: grid.x enumerates lower-triangular 128-tile pairs (scores)
//   TRIK  : limit K to (by+1)*128 (triangular attn in PV); heavy tiles first
//   QKV3  : N=3*1024 fused projection; epilogue routes q/k; the V third is
//           written TRANSPOSED (via smem restage) directly to C2 = V^T [b,h,s].
//   SCALE : multiply output by 1/32 (scores pre-scaling for softmax)
// Requires M%128==0, N%128==0, K%64==0.
// ---------------------------------------------------------------------------
#define LDSH 72                         // halves per smem row (64 + 8 pad)
#define STAGE_B (128 * LDSH * 2)        // bytes per operand stage (18432)
#define GSMEM2 (4 * STAGE_B)            // 2 stages x (A+B) = 73728 bytes
#define TRS 136                         // transposed-restage row stride (halves)

template <typename OutT, bool HASBIAS, bool TRIMAP, bool TRIK, bool QKV3, bool SCALE>
__global__ __launch_bounds__(256, 2) void mma_gemm_nt(
    const __half* __restrict__ A, const __half* __restrict__ B,
    const float* __restrict__ bias, OutT* __restrict__ C,
    int M, int N, int K,
    long long strA, long long strB, long long strC,
    OutT* __restrict__ C1, OutT* __restrict__ C2,
    const float* __restrict__ bias1, const float* __restrict__ bias2)
{
    int bx, by;
    if (TRIMAP) {
        const int idx = blockIdx.x;
        int r = (int)((sqrtf(8.0f * idx + 1.0f) - 1.0f) * 0.5f);
        while ((r + 1) * (r + 2) / 2 <= idx) r++;
        while (r * (r + 1) / 2 > idx) r--;
        by = r;
        bx = idx - r * (r + 1) / 2;
    } else {
        bx = blockIdx.x;
        by = TRIK ? (gridDim.y - 1 - blockIdx.y) : blockIdx.y;  // heavy first
    }

    extern __shared__ __half smh[];

    const int tid  = threadIdx.x;
    const int wid  = tid >> 5;
    const int lane = tid & 31;
    const int g    = lane >> 2;
    const int tig  = lane & 3;
    const int m0   = by * 128;
    const int n0   = bx * 128;
    const int wm   = (wid >> 2) * 64;   // 0 or 64
    const int wn   = (wid & 3) * 32;    // 0,32,64,96

    A += (long long)blockIdx.z * strA;
    B += (long long)blockIdx.z * strB;

    const int Kend = TRIK ? min(K, (by + 1) * 128) : K;
    const int T = Kend >> 6;  // 64-half k-chunks

    const uint32_t sBase = smem_u32(smh);

    // loader: 128 rows x 8 chunks(16B) per operand = 1024 chunks -> 4/thread
    const int lr0 = tid >> 3;           // 0..31 (+32*it)
    const int lc0 = tid & 7;            // 16B chunk in 128B row

    const int sel  = lane >> 3;
    const int srow = lane & 7;
    const int a_row  = wm + ((sel & 1) << 3) + srow;
    const int a_colh = (sel >> 1) << 3;
    const int b_row  = wn + (sel << 3) + srow;

    float acc[4][4][4];
#pragma unroll
    for (int i = 0; i < 4; i++)
#pragma unroll
        for (int j = 0; j < 4; j++)
#pragma unroll
            for (int r = 0; r < 4; r++) acc[i][j][r] = 0.0f;

    // ---- preload chunk 0 into stage 0 ----
#pragma unroll
    for (int it = 0; it < 4; it++) {
        const int row = lr0 + 32 * it;
        cp_async16(sBase + (uint32_t)(row * LDSH + lc0 * 8) * 2,
                   A + (size_t)(m0 + row) * K + lc0 * 8);
        cp_async16(sBase + STAGE_B + (uint32_t)(row * LDSH + lc0 * 8) * 2,
                   B + (size_t)(n0 + row) * K + lc0 * 8);
    }
    CP_COMMIT();

    for (int t = 0; t < T; t++) {
        const int buf = t & 1;

        asm volatile("cp.async.wait_group 0;" ::: "memory");
        __syncthreads();

        if (t + 1 < T) {
            const int nb = (t + 1) & 1;
            const int k0 = (t + 1) << 6;
            const uint32_t sa = sBase + (uint32_t)nb * (2 * STAGE_B);
            const uint32_t sb = sa + STAGE_B;
#pragma unroll
            for (int it = 0; it < 4; it++) {
                const int row = lr0 + 32 * it;
                cp_async16(sa + (uint32_t)(row * LDSH + lc0 * 8) * 2,
                           A + (size_t)(m0 + row) * K + k0 + lc0 * 8);
                cp_async16(sb + (uint32_t)(row * LDSH + lc0 * 8) * 2,
                           B + (size_t)(n0 + row) * K + k0 + lc0 * 8);
            }
            CP_COMMIT();
        }

        const uint32_t aB = sBase + (uint32_t)buf * (2 * STAGE_B);
        const uint32_t bB = aB + STAGE_B;
#pragma unroll
        for (int kk = 0; kk < 64; kk += 16) {
            uint32_t af[4][4], bf[4][2];
#pragma unroll
            for (int i = 0; i < 4; i++) {
                const uint32_t ad = aB + (uint32_t)((a_row + 16 * i) * LDSH + kk + a_colh) * 2;
                LDSM_X4(af[i][0], af[i][1], af[i][2], af[i][3], ad);
            }
            {
                const uint32_t bd = bB + (uint32_t)(b_row * LDSH + kk) * 2;
                LDSM_X4(bf[0][0], bf[1][0], bf[2][0], bf[3][0], bd);
                LDSM_X4(bf[0][1], bf[1][1], bf[2][1], bf[3][1], bd + 16);
            }
#pragma unroll
            for (int i = 0; i < 4; i++)
#pragma unroll
                for (int j = 0; j < 4; j++)
                    mma_f16(acc[i][j][0], acc[i][j][1], acc[i][j][2], acc[i][j][3],
                            af[i][0], af[i][1], af[i][2], af[i][3],
                            bf[j][0], bf[j][1]);
        }
    }

    // ---- epilogue ----
    if (QKV3 && (n0 >> 10) == 2) {
        // V third: write TRANSPOSED to C2 = V^T laid out [b][h][s].
        // m0 is the GLOBAL token index: b = m0/SS, s_local = m0%SS.
        // (tiles are 128 rows; SS%128==0 so a tile never straddles batches)
        __syncthreads();  // all warps done with math -> pipeline smem reusable
        const int hcol0 = n0 & 1023;                 // head-dim base of this tile
        const int batch   = m0 >> 11;                // m0 / SS
        const int s_base  = m0 & (SS - 1);           // m0 % SS
#pragma unroll
        for (int i = 0; i < 4; i++) {
            const int r0 = wm + i * 16 + g;          // local s index
#pragma unroll
            for (int j = 0; j < 4; j++) {
                const int col = wn + j * 8 + 2 * tig;  // local h index
                float v00 = acc[i][j][0], v01 = acc[i][j][1];
                float v10 = acc[i][j][2], v11 = acc[i][j][3];
                if (HASBIAS) {
                    const float b0 = bias2[hcol0 + col], b1 = bias2[hcol0 + col + 1];
                    v00 += b0; v01 += b1; v10 += b0; v11 += b1;
                }
                smh[(col    ) * TRS + r0    ] = __float2half_rn(v00);
                smh[(col + 1) * TRS + r0    ] = __float2half_rn(v01);
                smh[(col    ) * TRS + r0 + 8] = __float2half_rn(v10);
                smh[(col + 1) * TRS + r0 + 8] = __float2half_rn(v11);
            }
        }
        __syncthreads();
        // coalesced copy-out: 128 h-rows x 128 s = 2048 16B chunks, 8/thread
        __half* vt = (__half*)C2 + (size_t)batch * SS * HH;
#pragma unroll
        for (int c = 0; c < 8; c++) {
            const int idx = tid + c * 256;
            const int h  = idx >> 4;
            const int ch = idx & 15;
            uint4 val = *reinterpret_cast<const uint4*>(&smh[h * TRS + ch * 8]);
            *reinterpret_cast<uint4*>(
                vt + (size_t)(hcol0 + h) * SS + s_base + ch * 8) = val;
        }
        return;
    }

    OutT* dstp = C;
    const float* bp = bias;
    int ncol0 = n0;
    int NC = N;
    if (QKV3) {
        const int s = n0 >> 10;
        dstp = (s == 0) ? C : C1;
        bp   = (s == 0) ? bias : bias1;
        ncol0 = n0 & 1023;
        NC = HH;
    }
    dstp += (long long)blockIdx.z * strC;

#pragma unroll
    for (int i = 0; i < 4; i++) {
        const int r0 = m0 + wm + i * 16 + g;
#pragma unroll
        for (int j = 0; j < 4; j++) {
            const int col = ncol0 + wn + j * 8 + 2 * tig;
            float v00 = acc[i][j][0], v01 = acc[i][j][1];
            float v10 = acc[i][j][2], v11 = acc[i][j][3];
            if (HASBIAS) {
                const float b0 = bp[col], b1 = bp[col + 1];
                v00 += b0; v01 += b1; v10 += b0; v11 += b1;
            }
            if (SCALE) {
                v00 *= 0.03125f; v01 *= 0.03125f;
                v10 *= 0.03125f; v11 *= 0.03125f;
            }
            if (sizeof(OutT) == 2) {
                __half2 h0 = __floats2half2_rn(v00, v01);
                __half2 h1 = __floats2half2_rn(v10, v11);
                *reinterpret_cast<__half2*>((__half*)dstp + (size_t)r0 * NC + col) = h0;
                *reinterpret_cast<__half2*>((__half*)dstp + (size_t)(r0 + 8) * NC + col) = h1;
            } else {
                *reinterpret_cast<float2*>((float*)dstp + (size_t)r0 * NC + col) =
                    make_float2(v00, v01);
                *reinterpret_cast<float2*>((float*)dstp + (size_t)(r0 + 8) * NC + col) =
                    make_float2(v10, v11);
            }
        }
    }
}

// ---------------------------------------------------------------------------
// 2-pass online row softmax with causal + key mask.
// Scores arrive PRE-SCALED (GEMM epilogue did *1/32).
// ---------------------------------------------------------------------------
__global__ __launch_bounds__(256) void softmax_kernel(
    float* __restrict__ attn, __half* __restrict__ attn16,
    const int* __restrict__ mask)
{
    const int row = blockIdx.x;
    const int b = row >> 11;
    const int i = row & (SS - 1);
    float* p = attn + (size_t)b * SS * SS + (size_t)i * SS;
    __half* p16 = attn16 + (size_t)b * SS * SS + (size_t)i * SS;
    const int* mrow = mask + (size_t)b * SS;
    const int tid = threadIdx.x;

    float m = -FLT_MAX, s = 0.0f;
    for (int j = tid; j <= i; j += 256) {
        if (mrow[j] != 0) {
            float v = p[j];
            if (v > m) { s = s * __expf(m - v) + 1.0f; m = v; }
            else       { s += __expf(v - m); }
        }
    }

    __shared__ float sm[256], ss[256];
    sm[tid] = m; ss[tid] = s;
    __syncthreads();
    for (int st = 128; st > 0; st >>= 1) {
        if (tid < st) {
            float m1 = sm[tid], s1 = ss[tid];
            float m2 = sm[tid + st], s2 = ss[tid + st];
            float M = fmaxf(m1, m2);
            ss[tid] = s1 * __expf(m1 - M) + s2 * __expf(m2 - M);
            sm[tid] = M;
        }
        __syncthreads();
    }
    const float M = sm[0], S = ss[0];

    if (S == 0.0f) {  // fully masked row -> uniform (matches reference)
        const float u = 1.0f / SS;
        const __half uh = __float2half_rn(u);
        for (int j = tid; j < SS; j += 256) { p[j] = u; p16[j] = uh; }
        return;
    }

    const float inv = 1.0f / S;
    for (int j = tid; j <= i; j += 256) {
        float v = (mrow[j] != 0) ? __expf(p[j] - M) * inv : 0.0f;
        p[j] = v;
        p16[j] = __float2half_rn(v);
    }
    const __half z = __float2half_rn(0.0f);
    for (int j = i + 1 + tid; j < SS; j += 256) { p[j] = 0.0f; p16[j] = z; }
}

// ---------------------------------------------------------------------------
extern "C" void kernel_launch(void* const* d_in, const int* in_sizes, int n_in,
                              void* d_out, int out_size)
{
    const float* x    = (const float*)d_in[0];
    const int*   mask = (const int*)  d_in[1];
    const float* Wq   = (const float*)d_in[2];
    const float* bq   = (const float*)d_in[3];
    const float* Wk   = (const float*)d_in[4];
    const float* bk   = (const float*)d_in[5];
    const float* Wv   = (const float*)d_in[6];
    const float* bv   = (const float*)d_in[7];
    const float* Wo   = (const float*)d_in[8];
    const float* bo   = (const float*)d_in[9];

    __half *q, *k, *vt, *po, *attn16, *xh, *wh;
    float *attn_scratch;
    cudaGetSymbolAddress((void**)&q,  g_q);
    cudaGetSymbolAddress((void**)&k,  g_k);
    cudaGetSymbolAddress((void**)&vt, g_vt);
    cudaGetSymbolAddress((void**)&po, g_po);
    cudaGetSymbolAddress((void**)&attn_scratch, g_attn);
    cudaGetSymbolAddress((void**)&attn16, g_attn16);
    cudaGetSymbolAddress((void**)&xh, g_xh);
    cudaGetSymbolAddress((void**)&wh, g_wh);

    const long long OUT_N  = (long long)BB * SS * HH;
    const long long ATTN_N = (long long)BB * SS * SS;

    float* out_dst  = (float*)d_out;
    float* attn_dst = attn_scratch;
    if ((long long)out_size >= OUT_N + ATTN_N) {
        attn_dst = (float*)d_out + OUT_N;
    } else if ((long long)out_size == ATTN_N) {
        attn_dst = (float*)d_out;
        out_dst  = attn_scratch;  // unused sink
    }

    const int M_TOK = BB * SS;  // 8192
    __half* Woh = wh + (size_t)3 * HH * HH;

    cudaFuncSetAttribute(mma_gemm_nt<__half, true,  false, false, true,  false>,
        cudaFuncAttributeMaxDynamicSharedMemorySize, GSMEM2);
    cudaFuncSetAttribute(mma_gemm_nt<float,  false, true,  false, false, true>,
        cudaFuncAttributeMaxDynamicSharedMemorySize, GSMEM2);
    cudaFuncSetAttribute(mma_gemm_nt<__half, false, false, true,  false, false>,
        cudaFuncAttributeMaxDynamicSharedMemorySize, GSMEM2);
    cudaFuncSetAttribute(mma_gemm_nt<float,  true,  false, false, false, false>,
        cudaFuncAttributeMaxDynamicSharedMemorySize, GSMEM2);

    // 0) fp16 operand conversion
    {
        const int xn4 = (BB * SS * HH) / 4;
        const int wn4 = (HH * HH) / 4;
        half_copy_kernel<<<(xn4 + 255) / 256, 256>>>(x, xh, xn4);
        dim3 wg((wn4 + 255) / 256, 4);
        half_copy_w_kernel<<<wg, 256>>>(Wq, Wk, Wv, Wo, wh, wn4);
    }

    // 1) fused QKV projection; V third written transposed straight to vt
    {
        dim3 grid(3 * HH / 128, M_TOK / 128, 1);
        mma_gemm_nt<__half, true, false, false, true, false><<<grid, 256, GSMEM2>>>(
            xh, wh, bq, q, M_TOK, 3 * HH, HH, 0, 0, 0,
            k, vt, bk, bv);
    }

    // 2) scores = (Q @ K^T)/32; triangular grid over 128x128 tiles
    {
        const int ntiles = (SS / 128) * (SS / 128 + 1) / 2;  // 136
        dim3 grid(ntiles, 1, BB);
        mma_gemm_nt<float, false, true, false, false, true><<<grid, 256, GSMEM2>>>(
            q, k, nullptr, attn_dst, SS, SS, HH,
            (long long)SS * HH, (long long)SS * HH, (long long)SS * SS,
            nullptr, nullptr, nullptr, nullptr);
    }

    // 3) softmax (fp32 attn output + fp16 attn for PV)
    softmax_kernel<<<BB * SS, 256>>>(attn_dst, attn16, mask);

    // 4) PV: attn16 @ V, triangular K, heavy tiles first -> fp16 po
    {
        dim3 grid(HH / 128, SS / 128, BB);
        mma_gemm_nt<__half, false, false, true, false, false><<<grid, 256, GSMEM2>>>(
            attn16, vt, nullptr, po, SS, HH, SS,
            (long long)SS * SS, (long long)SS * HH, (long long)SS * HH,
            nullptr, nullptr, nullptr, nullptr);
    }

    // 5) output projection -> fp32 out + bias
    {
        dim3 grid(HH / 128, M_TOK / 128, 1);
        mma_gemm_nt<float, true, false, false, false, false><<<grid, 256, GSMEM2>>>(
            po, Woh, bo, out_dst, M_TOK, HH, HH, 0, 0, 0,
            nullptr, nullptr, nullptr, nullptr);
    }
}

// round 15
// speedup vs baseline: 1.0355x; 1.0208x over previous
#include <cuda_runtime.h>
#include <cuda_fp16.h>
#include <cstdint>
#include <float.h>

#define BB 4
#define SS 2048
#define HH 1024

// ---------------- scratch (allocation-free) ----------------
__device__ __half g_q [(size_t)BB * SS * HH];
__device__ __half g_k [(size_t)BB * SS * HH];
__device__ __half g_vt[(size_t)BB * SS * HH];      // V^T, produced by QKV epilogue
__device__ __half g_po[(size_t)BB * SS * HH];
__device__ float  g_attn[(size_t)BB * SS * SS];    // fp32 scores/attn
__device__ __half g_attn16[(size_t)BB * SS * SS];  // fp16 attn (PV operand)
__device__ __half g_xh [(size_t)BB * SS * HH];     // fp16 x
__device__ __half g_wh [(size_t)4 * HH * HH];      // fp16 Wq,Wk,Wv,Wo (contiguous)

__device__ __forceinline__ uint32_t smem_u32(const void* p) {
    uint32_t a;
    asm("{ .reg .u64 t; cvta.to.shared.u64 t, %1; cvt.u32.u64 %0, t; }" : "=r"(a) : "l"(p));
    return a;
}
__device__ __forceinline__ void cp_async16(uint32_t saddr, const void* gptr) {
    asm volatile("cp.async.cg.shared.global [%0], [%1], 16;"
                 :: "r"(saddr), "l"(gptr) : "memory");
}
#define CP_COMMIT() asm volatile("cp.async.commit_group;" ::: "memory")

#define LDSM_X4(r0, r1, r2, r3, addr)                                          \
    asm volatile("ldmatrix.sync.aligned.m8n8.x4.shared.b16 {%0,%1,%2,%3}, [%4];" \
        : "=r"(r0), "=r"(r1), "=r"(r2), "=r"(r3) : "r"(addr))

__device__ __forceinline__ void mma_f16(float& c0, float& c1, float& c2, float& c3,
                                        uint32_t a0, uint32_t a1, uint32_t a2, uint32_t a3,
                                        uint32_t b0, uint32_t b1) {
    asm volatile(
        "mma.sync.aligned.m16n8k16.row.col.f32.f16.f16.f32 "
        "{%0,%1,%2,%3}, {%4,%5,%6,%7}, {%8,%9}, {%0,%1,%2,%3};"
        : "+f"(c0), "+f"(c1), "+f"(c2), "+f"(c3)
        : "r"(a0), "r"(a1), "r"(a2), "r"(a3), "r"(b0), "r"(b1));
}

// ---------------------------------------------------------------------------
// half-convert copies (x single; weights batched over grid.y)
// ---------------------------------------------------------------------------
__global__ __launch_bounds__(256) void half_copy_kernel(
    const float* __restrict__ in, __half* __restrict__ out, int n4)
{
    int i = blockIdx.x * 256 + threadIdx.x;
    if (i < n4) {
        float4 v = reinterpret_cast<const float4*>(in)[i];
        __half2 lo = __floats2half2_rn(v.x, v.y);
        __half2 hi = __floats2half2_rn(v.z, v.w);
        uint2 pk;
        pk.x = *reinterpret_cast<uint32_t*>(&lo);
        pk.y = *reinterpret_cast<uint32_t*>(&hi);
        reinterpret_cast<uint2*>(out)[i] = pk;
    }
}

__global__ __launch_bounds__(256) void half_copy_w_kernel(
    const float* __restrict__ w0, const float* __restrict__ w1,
    const float* __restrict__ w2, const float* __restrict__ w3,
    __half* __restrict__ out, int n4)
{
    const float* in = (blockIdx.y == 0) ? w0 : (blockIdx.y == 1) ? w1
                    : (blockIdx.y == 2) ? w2 : w3;
    __half* o = out + (size_t)blockIdx.y * n4 * 4;
    int i = blockIdx.x * 256 + threadIdx.x;
    if (i < n4) {
        float4 v = reinterpret_cast<const float4*>(in)[i];
        __half2 lo = __floats2half2_rn(v.x, v.y);
        __half2 hi = __floats2half2_rn(v.z, v.w);
        uint2 pk;
        pk.x = *reinterpret_cast<uint32_t*>(&lo);
        pk.y = *reinterpret_cast<uint32_t*>(&hi);
        reinterpret_cast<uint2*>(o)[i] = pk;
    }
}

// ---------------------------------------------------------------------------
// NT fp16 tensor-core GEMM: C[M,N] = A[M,K] @ B^T (+bias fp32)
// CTA tile 128x128x64(halves), 8 warps (2x4), warp tile 64x32, m16n8k16,
// ldmatrix.x4 fragments, double-buffered BK=64 chunks, dynamic smem 72KB,
// __launch_bounds__(256,2) -> 2 CTAs/SM.
//   TRIMAP: grid.x enumerates lower-triangular 128-tile pairs (scores)
//   TRIK  : limit K to (by+1)*128 (triangular attn in PV); heavy tiles first
//   QKV3  : N=3*1024 fused projection; epilogue routes q/k; the V third is
//           written TRANSPOSED (via smem restage) directly to C2 = V^T [b,h,s].
//   SCALE : multiply output by 1/32 (scores pre-scaling for softmax)
// Requires M%128==0, N%128==0, K%64==0.
// ---------------------------------------------------------------------------
#define LDSH 72                         // halves per smem row (64 + 8 pad)
#define STAGE_B (128 * LDSH * 2)        // bytes per operand stage (18432)
#define GSMEM2 (4 * STAGE_B)            // 2 stages x (A+B) = 73728 bytes
#define TRS 136                         // transposed-restage row stride (halves)

template <typename OutT, bool HASBIAS, bool TRIMAP, bool TRIK, bool QKV3, bool SCALE>
__global__ __launch_bounds__(256, 2) void mma_gemm_nt(
    const __half* __restrict__ A, const __half* __restrict__ B,
    const float* __restrict__ bias, OutT* __restrict__ C,
    int M, int N, int K,
    long long strA, long long strB, long long strC,
    OutT* __restrict__ C1, OutT* __restrict__ C2,
    const float* __restrict__ bias1, const float* __restrict__ bias2)
{
    int bx, by;
    if (TRIMAP) {
        const int idx = blockIdx.x;
        int r = (int)((sqrtf(8.0f * idx + 1.0f) - 1.0f) * 0.5f);
        while ((r + 1) * (r + 2) / 2 <= idx) r++;
        while (r * (r + 1) / 2 > idx) r--;
        by = r;
        bx = idx - r * (r + 1) / 2;
    } else {
        bx = blockIdx.x;
        by = TRIK ? (gridDim.y - 1 - blockIdx.y) : blockIdx.y;  // heavy first
    }

    extern __shared__ __half smh[];

    const int tid  = threadIdx.x;
    const int wid  = tid >> 5;
    const int lane = tid & 31;
    const int g    = lane >> 2;
    const int tig  = lane & 3;
    const int m0   = by * 128;
    const int n0   = bx * 128;
    const int wm   = (wid >> 2) * 64;   // 0 or 64
    const int wn   = (wid & 3) * 32;    // 0,32,64,96

    A += (long long)blockIdx.z * strA;
    B += (long long)blockIdx.z * strB;

    const int Kend = TRIK ? min(K, (by + 1) * 128) : K;
    const int T = Kend >> 6;  // 64-half k-chunks

    const uint32_t sBase = smem_u32(smh);

    // loader: 128 rows x 8 chunks(16B) per operand = 1024 chunks -> 4/thread
    const int lr0 = tid >> 3;           // 0..31 (+32*it)
    const int lc0 = tid & 7;            // 16B chunk in 128B row

    const int sel  = lane >> 3;
    const int srow = lane & 7;
    const int a_row  = wm + ((sel & 1) << 3) + srow;
    const int a_colh = (sel >> 1) << 3;
    const int b_row  = wn + (sel << 3) + srow;

    float acc[4][4][4];
#pragma unroll
    for (int i = 0; i < 4; i++)
#pragma unroll
        for (int j = 0; j < 4; j++)
#pragma unroll
            for (int r = 0; r < 4; r++) acc[i][j][r] = 0.0f;

    // ---- preload chunk 0 into stage 0 ----
#pragma unroll
    for (int it = 0; it < 4; it++) {
        const int row = lr0 + 32 * it;
        cp_async16(sBase + (uint32_t)(row * LDSH + lc0 * 8) * 2,
                   A + (size_t)(m0 + row) * K + lc0 * 8);
        cp_async16(sBase + STAGE_B + (uint32_t)(row * LDSH + lc0 * 8) * 2,
                   B + (size_t)(n0 + row) * K + lc0 * 8);
    }
    CP_COMMIT();

    for (int t = 0; t < T; t++) {
        const int buf = t & 1;

        asm volatile("cp.async.wait_group 0;" ::: "memory");
        __syncthreads();

        if (t + 1 < T) {
            const int nb = (t + 1) & 1;
            const int k0 = (t + 1) << 6;
            const uint32_t sa = sBase + (uint32_t)nb * (2 * STAGE_B);
            const uint32_t sb = sa + STAGE_B;
#pragma unroll
            for (int it = 0; it < 4; it++) {
                const int row = lr0 + 32 * it;
                cp_async16(sa + (uint32_t)(row * LDSH + lc0 * 8) * 2,
                           A + (size_t)(m0 + row) * K + k0 + lc0 * 8);
                cp_async16(sb + (uint32_t)(row * LDSH + lc0 * 8) * 2,
                           B + (size_t)(n0 + row) * K + k0 + lc0 * 8);
            }
            CP_COMMIT();
        }

        const uint32_t aB = sBase + (uint32_t)buf * (2 * STAGE_B);
        const uint32_t bB = aB + STAGE_B;
#pragma unroll
        for (int kk = 0; kk < 64; kk += 16) {
            uint32_t af[4][4], bf[4][2];
#pragma unroll
            for (int i = 0; i < 4; i++) {
                const uint32_t ad = aB + (uint32_t)((a_row + 16 * i) * LDSH + kk + a_colh) * 2;
                LDSM_X4(af[i][0], af[i][1], af[i][2], af[i][3], ad);
            }
            {
                const uint32_t bd = bB + (uint32_t)(b_row * LDSH + kk) * 2;
                LDSM_X4(bf[0][0], bf[1][0], bf[2][0], bf[3][0], bd);
                LDSM_X4(bf[0][1], bf[1][1], bf[2][1], bf[3][1], bd + 16);
            }
#pragma unroll
            for (int i = 0; i < 4; i++)
#pragma unroll
                for (int j = 0; j < 4; j++)
                    mma_f16(acc[i][j][0], acc[i][j][1], acc[i][j][2], acc[i][j][3],
                            af[i][0], af[i][1], af[i][2], af[i][3],
                            bf[j][0], bf[j][1]);
        }
    }

    // ---- epilogue ----
    if (QKV3 && (n0 >> 10) == 2) {
        // V third: write TRANSPOSED to C2 = V^T laid out [b][h][s].
        __syncthreads();  // all warps done with math -> pipeline smem reusable
        const int hcol0 = n0 & 1023;
        const int batch   = m0 >> 11;                // m0 / SS
        const int s_base  = m0 & (SS - 1);           // m0 % SS
#pragma unroll
        for (int i = 0; i < 4; i++) {
            const int r0 = wm + i * 16 + g;          // local s index
#pragma unroll
            for (int j = 0; j < 4; j++) {
                const int col = wn + j * 8 + 2 * tig;  // local h index
                float v00 = acc[i][j][0], v01 = acc[i][j][1];
                float v10 = acc[i][j][2], v11 = acc[i][j][3];
                if (HASBIAS) {
                    const float b0 = bias2[hcol0 + col], b1 = bias2[hcol0 + col + 1];
                    v00 += b0; v01 += b1; v10 += b0; v11 += b1;
                }
                smh[(col    ) * TRS + r0    ] = __float2half_rn(v00);
                smh[(col + 1) * TRS + r0    ] = __float2half_rn(v01);
                smh[(col    ) * TRS + r0 + 8] = __float2half_rn(v10);
                smh[(col + 1) * TRS + r0 + 8] = __float2half_rn(v11);
            }
        }
        __syncthreads();
        __half* vt = (__half*)C2 + (size_t)batch * SS * HH;
#pragma unroll
        for (int c = 0; c < 8; c++) {
            const int idx = tid + c * 256;
            const int h  = idx >> 4;
            const int ch = idx & 15;
            uint4 val = *reinterpret_cast<const uint4*>(&smh[h * TRS + ch * 8]);
            *reinterpret_cast<uint4*>(
                vt + (size_t)(hcol0 + h) * SS + s_base + ch * 8) = val;
        }
        return;
    }

    OutT* dstp = C;
    const float* bp = bias;
    int ncol0 = n0;
    int NC = N;
    if (QKV3) {
        const int s = n0 >> 10;
        dstp = (s == 0) ? C : C1;
        bp   = (s == 0) ? bias : bias1;
        ncol0 = n0 & 1023;
        NC = HH;
    }
    dstp += (long long)blockIdx.z * strC;

#pragma unroll
    for (int i = 0; i < 4; i++) {
        const int r0 = m0 + wm + i * 16 + g;
#pragma unroll
        for (int j = 0; j < 4; j++) {
            const int col = ncol0 + wn + j * 8 + 2 * tig;
            float v00 = acc[i][j][0], v01 = acc[i][j][1];
            float v10 = acc[i][j][2], v11 = acc[i][j][3];
            if (HASBIAS) {
                const float b0 = bp[col], b1 = bp[col + 1];
                v00 += b0; v01 += b1; v10 += b0; v11 += b1;
            }
            if (SCALE) {
                v00 *= 0.03125f; v01 *= 0.03125f;
                v10 *= 0.03125f; v11 *= 0.03125f;
            }
            if (sizeof(OutT) == 2) {
                __half2 h0 = __floats2half2_rn(v00, v01);
                __half2 h1 = __floats2half2_rn(v10, v11);
                *reinterpret_cast<__half2*>((__half*)dstp + (size_t)r0 * NC + col) = h0;
                *reinterpret_cast<__half2*>((__half*)dstp + (size_t)(r0 + 8) * NC + col) = h1;
            } else {
                *reinterpret_cast<float2*>((float*)dstp + (size_t)r0 * NC + col) =
                    make_float2(v00, v01);
                *reinterpret_cast<float2*>((float*)dstp + (size_t)(r0 + 8) * NC + col) =
                    make_float2(v10, v11);
            }
        }
    }
}

// ---------------------------------------------------------------------------
// 2-pass online row softmax, fully vectorized (float4/int4 loads, float4 +
// packed-half stores). Scores arrive PRE-SCALED (*1/32 in GEMM epilogue).
// Pass 1: online (m,s) over vectors covering j<=i with key mask.
// Pass 2: one sweep over the FULL row writing fp32 + fp16 (zeros above diag).
// ---------------------------------------------------------------------------
__global__ __launch_bounds__(256) void softmax_kernel(
    float* __restrict__ attn, __half* __restrict__ attn16,
    const int* __restrict__ mask)
{
    const int row = blockIdx.x;
    const int b = row >> 11;
    const int i = row & (SS - 1);
    float* p = attn + (size_t)b * SS * SS + (size_t)i * SS;
    __half* p16 = attn16 + (size_t)b * SS * SS + (size_t)i * SS;
    const int* mrow = mask + (size_t)b * SS;
    const int tid = threadIdx.x;

    const float4* p4 = reinterpret_cast<const float4*>(p);
    const int4*   m4 = reinterpret_cast<const int4*>(mrow);
    const int vlast = i >> 2;  // vector index containing column i

    // ---- pass 1: per-thread online (m, s) over vectors [0, vlast] ----
    float m = -FLT_MAX, s = 0.0f;
    for (int v = tid; v <= vlast; v += 256) {
        float4 sv = p4[v];
        int4   mk = m4[v];
        const int j0 = v << 2;
        float vals[4] = {sv.x, sv.y, sv.z, sv.w};
        int   mks [4] = {mk.x, mk.y, mk.z, mk.w};
#pragma unroll
        for (int e = 0; e < 4; e++) {
            if (j0 + e <= i && mks[e] != 0) {
                float val = vals[e];
                if (val > m) { s = s * __expf(m - val) + 1.0f; m = val; }
                else         { s += __expf(val - m); }
            }
        }
    }

    __shared__ float sm[256], ss[256];
    sm[tid] = m; ss[tid] = s;
    __syncthreads();
    for (int st = 128; st > 0; st >>= 1) {
        if (tid < st) {
            float m1 = sm[tid], s1 = ss[tid];
            float m2 = sm[tid + st], s2 = ss[tid + st];
            float M = fmaxf(m1, m2);
            ss[tid] = s1 * __expf(m1 - M) + s2 * __expf(m2 - M);
            sm[tid] = M;
        }
        __syncthreads();
    }
    const float M = sm[0], S = ss[0];

    float4* po4 = reinterpret_cast<float4*>(p);
    uint2*  po16 = reinterpret_cast<uint2*>(p16);

    if (S == 0.0f) {  // fully masked row -> uniform (matches reference)
        const float u = 1.0f / SS;
        float4 uf = make_float4(u, u, u, u);
        __half2 uh2 = __floats2half2_rn(u, u);
        uint2 uh; uh.x = *reinterpret_cast<uint32_t*>(&uh2); uh.y = uh.x;
        for (int v = tid; v < SS / 4; v += 256) { po4[v] = uf; po16[v] = uh; }
        return;
    }

    // ---- pass 2: full-row sweep (values for j<=i, zeros above) ----
    const float inv = 1.0f / S;
    for (int v = tid; v < SS / 4; v += 256) {
        const int j0 = v << 2;
        float4 o;
        if (j0 + 3 <= i) {            // fully live vector
            float4 sv = p4[v];
            int4   mk = m4[v];
            o.x = (mk.x != 0) ? __expf(sv.x - M) * inv : 0.0f;
            o.y = (mk.y != 0) ? __expf(sv.y - M) * inv : 0.0f;
            o.z = (mk.z != 0) ? __expf(sv.z - M) * inv : 0.0f;
            o.w = (mk.w != 0) ? __expf(sv.w - M) * inv : 0.0f;
        } else if (j0 > i) {          // fully above diagonal
            o = make_float4(0.0f, 0.0f, 0.0f, 0.0f);
        } else {                      // straddles the diagonal
            float4 sv = p4[v];
            int4   mk = m4[v];
            o.x = (j0     <= i && mk.x != 0) ? __expf(sv.x - M) * inv : 0.0f;
            o.y = (j0 + 1 <= i && mk.y != 0) ? __expf(sv.y - M) * inv : 0.0f;
            o.z = (j0 + 2 <= i && mk.z != 0) ? __expf(sv.z - M) * inv : 0.0f;
            o.w = (j0 + 3 <= i && mk.w != 0) ? __expf(sv.w - M) * inv : 0.0f;
        }
        po4[v] = o;
        __half2 h0 = __floats2half2_rn(o.x, o.y);
        __half2 h1 = __floats2half2_rn(o.z, o.w);
        uint2 pk;
        pk.x = *reinterpret_cast<uint32_t*>(&h0);
        pk.y = *reinterpret_cast<uint32_t*>(&h1);
        po16[v] = pk;
    }
}

// ---------------------------------------------------------------------------
extern "C" void kernel_launch(void* const* d_in, const int* in_sizes, int n_in,
                              void* d_out, int out_size)
{
    const float* x    = (const float*)d_in[0];
    const int*   mask = (const int*)  d_in[1];
    const float* Wq   = (const float*)d_in[2];
    const float* bq   = (const float*)d_in[3];
    const float* Wk   = (const float*)d_in[4];
    const float* bk   = (const float*)d_in[5];
    const float* Wv   = (const float*)d_in[6];
    const float* bv   = (const float*)d_in[7];
    const float* Wo   = (const float*)d_in[8];
    const float* bo   = (const float*)d_in[9];

    __half *q, *k, *vt, *po, *attn16, *xh, *wh;
    float *attn_scratch;
    cudaGetSymbolAddress((void**)&q,  g_q);
    cudaGetSymbolAddress((void**)&k,  g_k);
    cudaGetSymbolAddress((void**)&vt, g_vt);
    cudaGetSymbolAddress((void**)&po, g_po);
    cudaGetSymbolAddress((void**)&attn_scratch, g_attn);
    cudaGetSymbolAddress((void**)&attn16, g_attn16);
    cudaGetSymbolAddress((void**)&xh, g_xh);
    cudaGetSymbolAddress((void**)&wh, g_wh);

    const long long OUT_N  = (long long)BB * SS * HH;
    const long long ATTN_N = (long long)BB * SS * SS;

    float* out_dst  = (float*)d_out;
    float* attn_dst = attn_scratch;
    if ((long long)out_size >= OUT_N + ATTN_N) {
        attn_dst = (float*)d_out + OUT_N;
    } else if ((long long)out_size == ATTN_N) {
        attn_dst = (float*)d_out;
        out_dst  = attn_scratch;  // unused sink
    }

    const int M_TOK = BB * SS;  // 8192
    __half* Woh = wh + (size_t)3 * HH * HH;

    cudaFuncSetAttribute(mma_gemm_nt<__half, true,  false, false, true,  false>,
        cudaFuncAttributeMaxDynamicSharedMemorySize, GSMEM2);
    cudaFuncSetAttribute(mma_gemm_nt<float,  false, true,  false, false, true>,
        cudaFuncAttributeMaxDynamicSharedMemorySize, GSMEM2);
    cudaFuncSetAttribute(mma_gemm_nt<__half, false, false, true,  false, false>,
        cudaFuncAttributeMaxDynamicSharedMemorySize, GSMEM2);
    cudaFuncSetAttribute(mma_gemm_nt<float,  true,  false, false, false, false>,
        cudaFuncAttributeMaxDynamicSharedMemorySize, GSMEM2);

    // 0) fp16 operand conversion
    {
        const int xn4 = (BB * SS * HH) / 4;
        const int wn4 = (HH * HH) / 4;
        half_copy_kernel<<<(xn4 + 255) / 256, 256>>>(x, xh, xn4);
        dim3 wg((wn4 + 255) / 256, 4);
        half_copy_w_kernel<<<wg, 256>>>(Wq, Wk, Wv, Wo, wh, wn4);
    }

    // 1) fused QKV projection; V third written transposed straight to vt
    {
        dim3 grid(3 * HH / 128, M_TOK / 128, 1);
        mma_gemm_nt<__half, true, false, false, true, false><<<grid, 256, GSMEM2>>>(
            xh, wh, bq, q, M_TOK, 3 * HH, HH, 0, 0, 0,
            k, vt, bk, bv);
    }

    // 2) scores = (Q @ K^T)/32; triangular grid over 128x128 tiles
    {
        const int ntiles = (SS / 128) * (SS / 128 + 1) / 2;  // 136
        dim3 grid(ntiles, 1, BB);
        mma_gemm_nt<float, false, true, false, false, true><<<grid, 256, GSMEM2>>>(
            q, k, nullptr, attn_dst, SS, SS, HH,
            (long long)SS * HH, (long long)SS * HH, (long long)SS * SS,
            nullptr, nullptr, nullptr, nullptr);
    }

    // 3) softmax (vectorized; fp32 attn output + fp16 attn for PV)
    softmax_kernel<<<BB * SS, 256>>>(attn_dst, attn16, mask);

    // 4) PV: attn16 @ V, triangular K, heavy tiles first -> fp16 po
    {
        dim3 grid(HH / 128, SS / 128, BB);
        mma_gemm_nt<__half, false, false, true, false, false><<<grid, 256, GSMEM2>>>(
            attn16, vt, nullptr, po, SS, HH, SS,
            (long long)SS * SS, (long long)SS * HH, (long long)SS * HH,
            nullptr, nullptr, nullptr, nullptr);
    }

    // 5) output projection -> fp32 out + bias
    {
        dim3 grid(HH / 128, M_TOK / 128, 1);
        mma_gemm_nt<float, true, false, false, false, false><<<grid, 256, GSMEM2>>>(
            po, Woh, bo, out_dst, M_TOK, HH, HH, 0, 0, 0,
            nullptr, nullptr, nullptr, nullptr);
    }
}

// round 17
// speedup vs baseline: 1.0494x; 1.0134x over previous
#include <cuda_runtime.h>
#include <cuda_fp16.h>
#include <cstdint>
#include <float.h>

#define BB 4
#define SS 2048
#define HH 1024

// ---------------- scratch (allocation-free) ----------------
__device__ __half g_q [(size_t)BB * SS * HH];
__device__ __half g_k [(size_t)BB * SS * HH];
__device__ __half g_vt[(size_t)BB * SS * HH];      // V^T, produced by QKV epilogue
__device__ __half g_po[(size_t)BB * SS * HH];
__device__ float  g_attn[(size_t)BB * SS * SS];    // fp32 scores/attn
__device__ __half g_attn16[(size_t)BB * SS * SS];  // fp16 attn (PV operand);
                                                   // zero-init, upper triangle
                                                   // beyond diag vec never dirtied
__device__ __half g_xh [(size_t)BB * SS * HH];     // fp16 x
__device__ __half g_wh [(size_t)4 * HH * HH];      // fp16 Wq,Wk,Wv,Wo (contiguous)

__device__ __forceinline__ uint32_t smem_u32(const void* p) {
    uint32_t a;
    asm("{ .reg .u64 t; cvta.to.shared.u64 t, %1; cvt.u32.u64 %0, t; }" : "=r"(a) : "l"(p));
    return a;
}
__device__ __forceinline__ void cp_async16(uint32_t saddr, const void* gptr) {
    asm volatile("cp.async.cg.shared.global [%0], [%1], 16;"
                 :: "r"(saddr), "l"(gptr) : "memory");
}
#define CP_COMMIT() asm volatile("cp.async.commit_group;" ::: "memory")

#define LDSM_X4(r0, r1, r2, r3, addr)                                          \
    asm volatile("ldmatrix.sync.aligned.m8n8.x4.shared.b16 {%0,%1,%2,%3}, [%4];" \
        : "=r"(r0), "=r"(r1), "=r"(r2), "=r"(r3) : "r"(addr))

__device__ __forceinline__ void mma_f16(float& c0, float& c1, float& c2, float& c3,
                                        uint32_t a0, uint32_t a1, uint32_t a2, uint32_t a3,
                                        uint32_t b0, uint32_t b1) {
    asm volatile(
        "mma.sync.aligned.m16n8k16.row.col.f32.f16.f16.f32 "
        "{%0,%1,%2,%3}, {%4,%5,%6,%7}, {%8,%9}, {%0,%1,%2,%3};"
        : "+f"(c0), "+f"(c1), "+f"(c2), "+f"(c3)
        : "r"(a0), "r"(a1), "r"(a2), "r"(a3), "r"(b0), "r"(b1));
}

// ---------------------------------------------------------------------------
// Fused half-convert: one kernel for x (xn4 vectors) + 4 weights (wn4 each).
// ---------------------------------------------------------------------------
__global__ __launch_bounds__(256) void half_convert_all_kernel(
    const float* __restrict__ x,  __half* __restrict__ xh,  int xn4,
    const float* __restrict__ w0, const float* __restrict__ w1,
    const float* __restrict__ w2, const float* __restrict__ w3,
    __half* __restrict__ wh, int wn4)
{
    int i = blockIdx.x * 256 + threadIdx.x;
    const float* in;
    __half* out;
    int idx;
    if (i < xn4) {
        in = x; out = xh; idx = i;
    } else {
        int r = i - xn4;
        int w = r / wn4;
        if (w >= 4) return;
        idx = r - w * wn4;
        in = (w == 0) ? w0 : (w == 1) ? w1 : (w == 2) ? w2 : w3;
        out = wh + (size_t)w * wn4 * 4;
    }
    float4 v = reinterpret_cast<const float4*>(in)[idx];
    __half2 lo = __floats2half2_rn(v.x, v.y);
    __half2 hi = __floats2half2_rn(v.z, v.w);
    uint2 pk;
    pk.x = *reinterpret_cast<uint32_t*>(&lo);
    pk.y = *reinterpret_cast<uint32_t*>(&hi);
    reinterpret_cast<uint2*>(out)[idx] = pk;
}

// ---------------------------------------------------------------------------
// NT fp16 tensor-core GEMM: C[M,N] = A[M,K] @ B^T (+bias fp32)
// CTA tile 128x128x64(halves), 8 warps (2x4), warp tile 64x32, m16n8k16,
// ldmatrix.x4 fragments, double-buffered BK=64 chunks, dynamic smem 72KB,
// __launch_bounds__(256,2) -> 2 CTAs/SM.
//   TRIMAP: grid.x enumerates lower-triangular 128-tile pairs (scores)
//   TRIK  : limit K to (by+1)*128 (triangular attn in PV); heavy tiles first
//   QKV3  : N=3*1024 fused projection; epilogue routes q/k; the V third is
//           written TRANSPOSED (via smem restage) directly to C2 = V^T [b,h,s].
//   SCALE : multiply output by 1/32 (scores pre-scaling for softmax)
// Requires M%128==0, N%128==0, K%64==0.
// ---------------------------------------------------------------------------
#define LDSH 72                         // halves per smem row (64 + 8 pad)
#define STAGE_B (128 * LDSH * 2)        // bytes per operand stage (18432)
#define GSMEM2 (4 * STAGE_B)            // 2 stages x (A+B) = 73728 bytes
#define TRS 136                         // transposed-restage row stride (halves)

template <typename OutT, bool HASBIAS, bool TRIMAP, bool TRIK, bool QKV3, bool SCALE>
__global__ __launch_bounds__(256, 2) void mma_gemm_nt(
    const __half* __restrict__ A, const __half* __restrict__ B,
    const float* __restrict__ bias, OutT* __restrict__ C,
    int M, int N, int K,
    long long strA, long long strB, long long strC,
    OutT* __restrict__ C1, OutT* __restrict__ C2,
    const float* __restrict__ bias1, const float* __restrict__ bias2)
{
    int bx, by;
    if (TRIMAP) {
        const int idx = blockIdx.x;
        int r = (int)((sqrtf(8.0f * idx + 1.0f) - 1.0f) * 0.5f);
        while ((r + 1) * (r + 2) / 2 <= idx) r++;
        while (r * (r + 1) / 2 > idx) r--;
        by = r;
        bx = idx - r * (r + 1) / 2;
    } else {
        bx = blockIdx.x;
        by = TRIK ? (gridDim.y - 1 - blockIdx.y) : blockIdx.y;  // heavy first
    }

    extern __shared__ __half smh[];

    const int tid  = threadIdx.x;
    const int wid  = tid >> 5;
    const int lane = tid & 31;
    const int g    = lane >> 2;
    const int tig  = lane & 3;
    const int m0   = by * 128;
    const int n0   = bx * 128;
    const int wm   = (wid >> 2) * 64;   // 0 or 64
    const int wn   = (wid & 3) * 32;    // 0,32,64,96

    A += (long long)blockIdx.z * strA;
    B += (long long)blockIdx.z * strB;

    const int Kend = TRIK ? min(K, (by + 1) * 128) : K;
    const int T = Kend >> 6;  // 64-half k-chunks

    const uint32_t sBase = smem_u32(smh);

    // loader: 128 rows x 8 chunks(16B) per operand = 1024 chunks -> 4/thread
    const int lr0 = tid >> 3;           // 0..31 (+32*it)
    const int lc0 = tid & 7;            // 16B chunk in 128B row

    const int sel  = lane >> 3;
    const int srow = lane & 7;
    const int a_row  = wm + ((sel & 1) << 3) + srow;
    const int a_colh = (sel >> 1) << 3;
    const int b_row  = wn + (sel << 3) + srow;

    float acc[4][4][4];
#pragma unroll
    for (int i = 0; i < 4; i++)
#pragma unroll
        for (int j = 0; j < 4; j++)
#pragma unroll
            for (int r = 0; r < 4; r++) acc[i][j][r] = 0.0f;

    // ---- preload chunk 0 into stage 0 ----
#pragma unroll
    for (int it = 0; it < 4; it++) {
        const int row = lr0 + 32 * it;
        cp_async16(sBase + (uint32_t)(row * LDSH + lc0 * 8) * 2,
                   A + (size_t)(m0 + row) * K + lc0 * 8);
        cp_async16(sBase + STAGE_B + (uint32_t)(row * LDSH + lc0 * 8) * 2,
                   B + (size_t)(n0 + row) * K + lc0 * 8);
    }
    CP_COMMIT();

    for (int t = 0; t < T; t++) {
        const int buf = t & 1;

        asm volatile("cp.async.wait_group 0;" ::: "memory");
        __syncthreads();

        if (t + 1 < T) {
            const int nb = (t + 1) & 1;
            const int k0 = (t + 1) << 6;
            const uint32_t sa = sBase + (uint32_t)nb * (2 * STAGE_B);
            const uint32_t sb = sa + STAGE_B;
#pragma unroll
            for (int it = 0; it < 4; it++) {
                const int row = lr0 + 32 * it;
                cp_async16(sa + (uint32_t)(row * LDSH + lc0 * 8) * 2,
                           A + (size_t)(m0 + row) * K + k0 + lc0 * 8);
                cp_async16(sb + (uint32_t)(row * LDSH + lc0 * 8) * 2,
                           B + (size_t)(n0 + row) * K + k0 + lc0 * 8);
            }
            CP_COMMIT();
        }

        const uint32_t aB = sBase + (uint32_t)buf * (2 * STAGE_B);
        const uint32_t bB = aB + STAGE_B;
#pragma unroll
        for (int kk = 0; kk < 64; kk += 16) {
            uint32_t af[4][4], bf[4][2];
#pragma unroll
            for (int i = 0; i < 4; i++) {
                const uint32_t ad = aB + (uint32_t)((a_row + 16 * i) * LDSH + kk + a_colh) * 2;
                LDSM_X4(af[i][0], af[i][1], af[i][2], af[i][3], ad);
            }
            {
                const uint32_t bd = bB + (uint32_t)(b_row * LDSH + kk) * 2;
                LDSM_X4(bf[0][0], bf[1][0], bf[2][0], bf[3][0], bd);
                LDSM_X4(bf[0][1], bf[1][1], bf[2][1], bf[3][1], bd + 16);
            }
#pragma unroll
            for (int i = 0; i < 4; i++)
#pragma unroll
                for (int j = 0; j < 4; j++)
                    mma_f16(acc[i][j][0], acc[i][j][1], acc[i][j][2], acc[i][j][3],
                            af[i][0], af[i][1], af[i][2], af[i][3],
                            bf[j][0], bf[j][1]);
        }
    }

    // ---- epilogue ----
    if (QKV3 && (n0 >> 10) == 2) {
        // V third: write TRANSPOSED to C2 = V^T laid out [b][h][s].
        __syncthreads();  // all warps done with math -> pipeline smem reusable
        const int hcol0 = n0 & 1023;
        const int batch   = m0 >> 11;                // m0 / SS
        const int s_base  = m0 & (SS - 1);           // m0 % SS
#pragma unroll
        for (int i = 0; i < 4; i++) {
            const int r0 = wm + i * 16 + g;          // local s index
#pragma unroll
            for (int j = 0; j < 4; j++) {
                const int col = wn + j * 8 + 2 * tig;  // local h index
                float v00 = acc[i][j][0], v01 = acc[i][j][1];
                float v10 = acc[i][j][2], v11 = acc[i][j][3];
                if (HASBIAS) {
                    const float b0 = bias2[hcol0 + col], b1 = bias2[hcol0 + col + 1];
                    v00 += b0; v01 += b1; v10 += b0; v11 += b1;
                }
                smh[(col    ) * TRS + r0    ] = __float2half_rn(v00);
                smh[(col + 1) * TRS + r0    ] = __float2half_rn(v01);
                smh[(col    ) * TRS + r0 + 8] = __float2half_rn(v10);
                smh[(col + 1) * TRS + r0 + 8] = __float2half_rn(v11);
            }
        }
        __syncthreads();
        __half* vt = (__half*)C2 + (size_t)batch * SS * HH;
#pragma unroll
        for (int c = 0; c < 8; c++) {
            const int idx = tid + c * 256;
            const int h  = idx >> 4;
            const int ch = idx & 15;
            uint4 val = *reinterpret_cast<const uint4*>(&smh[h * TRS + ch * 8]);
            *reinterpret_cast<uint4*>(
                vt + (size_t)(hcol0 + h) * SS + s_base + ch * 8) = val;
        }
        return;
    }

    OutT* dstp = C;
    const float* bp = bias;
    int ncol0 = n0;
    int NC = N;
    if (QKV3) {
        const int s = n0 >> 10;
        dstp = (s == 0) ? C : C1;
        bp   = (s == 0) ? bias : bias1;
        ncol0 = n0 & 1023;
        NC = HH;
    }
    dstp += (long long)blockIdx.z * strC;

#pragma unroll
    for (int i = 0; i < 4; i++) {
        const int r0 = m0 + wm + i * 16 + g;
#pragma unroll
        for (int j = 0; j < 4; j++) {
            const int col = ncol0 + wn + j * 8 + 2 * tig;
            float v00 = acc[i][j][0], v01 = acc[i][j][1];
            float v10 = acc[i][j][2], v11 = acc[i][j][3];
            if (HASBIAS) {
                const float b0 = bp[col], b1 = bp[col + 1];
                v00 += b0; v01 += b1; v10 += b0; v11 += b1;
            }
            if (SCALE) {
                v00 *= 0.03125f; v01 *= 0.03125f;
                v10 *= 0.03125f; v11 *= 0.03125f;
            }
            if (sizeof(OutT) == 2) {
                __half2 h0 = __floats2half2_rn(v00, v01);
                __half2 h1 = __floats2half2_rn(v10, v11);
                *reinterpret_cast<__half2*>((__half*)dstp + (size_t)r0 * NC + col) = h0;
                *reinterpret_cast<__half2*>((__half*)dstp + (size_t)(r0 + 8) * NC + col) = h1;
            } else {
                *reinterpret_cast<float2*>((float*)dstp + (size_t)r0 * NC + col) =
                    make_float2(v00, v01);
                *reinterpret_cast<float2*>((float*)dstp + (size_t)(r0 + 8) * NC + col) =
                    make_float2(v10, v11);
            }
        }
    }
}

// ---------------------------------------------------------------------------
// 2-pass online row softmax, vectorized. Scores PRE-SCALED (*1/32 in GEMM).
// fp32 output: FULL row (may alias d_out, poisoned each run).
// fp16 output: only vectors v <= vlast — g_attn16 is zero-initialized scratch
// and the strictly-upper vectors are never dirtied, so they stay 0 across
// graph replays (deterministic).
// ---------------------------------------------------------------------------
__global__ __launch_bounds__(256) void softmax_kernel(
    float* __restrict__ attn, __half* __restrict__ attn16,
    const int* __restrict__ mask)
{
    const int row = blockIdx.x;
    const int b = row >> 11;
    const int i = row & (SS - 1);
    float* p = attn + (size_t)b * SS * SS + (size_t)i * SS;
    __half* p16 = attn16 + (size_t)b * SS * SS + (size_t)i * SS;
    const int* mrow = mask + (size_t)b * SS;
    const int tid = threadIdx.x;

    const float4* p4 = reinterpret_cast<const float4*>(p);
    const int4*   m4 = reinterpret_cast<const int4*>(mrow);
    const int vlast = i >> 2;  // vector index containing column i

    // ---- pass 1: per-thread online (m, s) over vectors [0, vlast] ----
    float m = -FLT_MAX, s = 0.0f;
    for (int v = tid; v <= vlast; v += 256) {
        float4 sv = p4[v];
        int4   mk = m4[v];
        const int j0 = v << 2;
        float vals[4] = {sv.x, sv.y, sv.z, sv.w};
        int   mks [4] = {mk.x, mk.y, mk.z, mk.w};
#pragma unroll
        for (int e = 0; e < 4; e++) {
            if (j0 + e <= i && mks[e] != 0) {
                float val = vals[e];
                if (val > m) { s = s * __expf(m - val) + 1.0f; m = val; }
                else         { s += __expf(val - m); }
            }
        }
    }

    __shared__ float sm[256], ss[256];
    sm[tid] = m; ss[tid] = s;
    __syncthreads();
    for (int st = 128; st > 0; st >>= 1) {
        if (tid < st) {
            float m1 = sm[tid], s1 = ss[tid];
            float m2 = sm[tid + st], s2 = ss[tid + st];
            float M = fmaxf(m1, m2);
            ss[tid] = s1 * __expf(m1 - M) + s2 * __expf(m2 - M);
            sm[tid] = M;
        }
        __syncthreads();
    }
    const float M = sm[0], S = ss[0];

    float4* po4 = reinterpret_cast<float4*>(p);
    uint2*  po16 = reinterpret_cast<uint2*>(p16);

    if (S == 0.0f) {  // fully masked row -> uniform (matches reference)
        const float u = 1.0f / SS;
        float4 uf = make_float4(u, u, u, u);
        __half2 uh2 = __floats2half2_rn(u, u);
        uint2 uh; uh.x = *reinterpret_cast<uint32_t*>(&uh2); uh.y = uh.x;
        for (int v = tid; v < SS / 4; v += 256) { po4[v] = uf; po16[v] = uh; }
        return;
    }

    // ---- pass 2: fp32 full row; fp16 only up to the diagonal vector ----
    const float inv = 1.0f / S;
    for (int v = tid; v < SS / 4; v += 256) {
        const int j0 = v << 2;
        float4 o;
        if (j0 + 3 <= i) {            // fully live vector
            float4 sv = p4[v];
            int4   mk = m4[v];
            o.x = (mk.x != 0) ? __expf(sv.x - M) * inv : 0.0f;
            o.y = (mk.y != 0) ? __expf(sv.y - M) * inv : 0.0f;
            o.z = (mk.z != 0) ? __expf(sv.z - M) * inv : 0.0f;
            o.w = (mk.w != 0) ? __expf(sv.w - M) * inv : 0.0f;
        } else if (j0 > i) {          // fully above diagonal
            o = make_float4(0.0f, 0.0f, 0.0f, 0.0f);
        } else {                      // straddles the diagonal
            float4 sv = p4[v];
            int4   mk = m4[v];
            o.x = (j0     <= i && mk.x != 0) ? __expf(sv.x - M) * inv : 0.0f;
            o.y = (j0 + 1 <= i && mk.y != 0) ? __expf(sv.y - M) * inv : 0.0f;
            o.z = (j0 + 2 <= i && mk.z != 0) ? __expf(sv.z - M) * inv : 0.0f;
            o.w = (j0 + 3 <= i && mk.w != 0) ? __expf(sv.w - M) * inv : 0.0f;
        }
        po4[v] = o;
        if (v <= vlast) {  // fp16 zeros above diagonal persist from zero-init
            __half2 h0 = __floats2half2_rn(o.x, o.y);
            __half2 h1 = __floats2half2_rn(o.z, o.w);
            uint2 pk;
            pk.x = *reinterpret_cast<uint32_t*>(&h0);
            pk.y = *reinterpret_cast<uint32_t*>(&h1);
            po16[v] = pk;
        }
    }
}

// ---------------------------------------------------------------------------
extern "C" void kernel_launch(void* const* d_in, const int* in_sizes, int n_in,
                              void* d_out, int out_size)
{
    const float* x    = (const float*)d_in[0];
    const int*   mask = (const int*)  d_in[1];
    const float* Wq   = (const float*)d_in[2];
    const float* bq   = (const float*)d_in[3];
    const float* Wk   = (const float*)d_in[4];
    const float* bk   = (const float*)d_in[5];
    const float* Wv   = (const float*)d_in[6];
    const float* bv   = (const float*)d_in[7];
    const float* Wo   = (const float*)d_in[8];
    const float* bo   = (const float*)d_in[9];

    __half *q, *k, *vt, *po, *attn16, *xh, *wh;
    float *attn_scratch;
    cudaGetSymbolAddress((void**)&q,  g_q);
    cudaGetSymbolAddress((void**)&k,  g_k);
    cudaGetSymbolAddress((void**)&vt, g_vt);
    cudaGetSymbolAddress((void**)&po, g_po);
    cudaGetSymbolAddress((void**)&attn_scratch, g_attn);
    cudaGetSymbolAddress((void**)&attn16, g_attn16);
    cudaGetSymbolAddress((void**)&xh, g_xh);
    cudaGetSymbolAddress((void**)&wh, g_wh);

    const long long OUT_N  = (long long)BB * SS * HH;
    const long long ATTN_N = (long long)BB * SS * SS;

    float* out_dst  = (float*)d_out;
    float* attn_dst = attn_scratch;
    if ((long long)out_size >= OUT_N + ATTN_N) {
        attn_dst = (float*)d_out + OUT_N;
    } else if ((long long)out_size == ATTN_N) {
        attn_dst = (float*)d_out;
        out_dst  = attn_scratch;  // unused sink
    }

    const int M_TOK = BB * SS;  // 8192
    __half* Woh = wh + (size_t)3 * HH * HH;

    cudaFuncSetAttribute(mma_gemm_nt<__half, true,  false, false, true,  false>,
        cudaFuncAttributeMaxDynamicSharedMemorySize, GSMEM2);
    cudaFuncSetAttribute(mma_gemm_nt<float,  false, true,  false, false, true>,
        cudaFuncAttributeMaxDynamicSharedMemorySize, GSMEM2);
    cudaFuncSetAttribute(mma_gemm_nt<__half, false, false, true,  false, false>,
        cudaFuncAttributeMaxDynamicSharedMemorySize, GSMEM2);
    cudaFuncSetAttribute(mma_gemm_nt<float,  true,  false, false, false, false>,
        cudaFuncAttributeMaxDynamicSharedMemorySize, GSMEM2);

    // 0) fp16 operand conversion (one launch: x + all weights)
    {
        const int xn4 = (BB * SS * HH) / 4;   // 2097152
        const int wn4 = (HH * HH) / 4;        //  262144
        const int total4 = xn4 + 4 * wn4;
        half_convert_all_kernel<<<(total4 + 255) / 256, 256>>>(
            x, xh, xn4, Wq, Wk, Wv, Wo, wh, wn4);
    }

    // 1) fused QKV projection; V third written transposed straight to vt
    {
        dim3 grid(3 * HH / 128, M_TOK / 128, 1);
        mma_gemm_nt<__half, true, false, false, true, false><<<grid, 256, GSMEM2>>>(
            xh, wh, bq, q, M_TOK, 3 * HH, HH, 0, 0, 0,
            k, vt, bk, bv);
    }

    // 2) scores = (Q @ K^T)/32; triangular grid over 128x128 tiles
    {
        const int ntiles = (SS / 128) * (SS / 128 + 1) / 2;  // 136
        dim3 grid(ntiles, 1, BB);
        mma_gemm_nt<float, false, true, false, false, true><<<grid, 256, GSMEM2>>>(
            q, k, nullptr, attn_dst, SS, SS, HH,
            (long long)SS * HH, (long long)SS * HH, (long long)SS * SS,
            nullptr, nullptr, nullptr, nullptr);
    }

    // 3) softmax (vectorized; fp32 attn output + fp16 triangle for PV)
    softmax_kernel<<<BB * SS, 256>>>(attn_dst, attn16, mask);

    // 4) PV: attn16 @ V, triangular K, heavy tiles first -> fp16 po
    {
        dim3 grid(HH / 128, SS / 128, BB);
        mma_gemm_nt<__half, false, false, true, false, false><<<grid, 256, GSMEM2>>>(
            attn16, vt, nullptr, po, SS, HH, SS,
            (long long)SS * SS, (long long)SS * HH, (long long)SS * HH,
            nullptr, nullptr, nullptr, nullptr);
    }

    // 5) output projection -> fp32 out + bias
    {
        dim3 grid(HH / 128, M_TOK / 128, 1);
        mma_gemm_nt<float, true, false, false, false, false><<<grid, 256, GSMEM2>>>(
            po, Woh, bo, out_dst, M_TOK, HH, HH, 0, 0, 0,
            nullptr, nullptr, nullptr, nullptr);
    }
}